// round 1
// baseline (speedup 1.0000x reference)
#include <cuda_runtime.h>

#define B_    4
#define C_    256
#define H_    96
#define W_    96
#define HW_   (H_ * W_)     // 9216
#define N_    (HW_ / 2)     // 4608
#define FOUT_ 32
#define DV_   256
#define TOT_  (B_ * C_ * HW_)  // 9,437,184

// ---- scratch (device globals; no allocation allowed) ----
__device__ float g_Q[B_ * N_ * FOUT_];   // (b, n, 32)
__device__ float g_K[B_ * N_ * FOUT_];   // (b, n, 32)
__device__ float g_V[B_ * N_ * DV_];     // (b, n, 256)
__device__ float g_O[B_ * N_ * DV_];     // (b, n, 256)
__device__ int   g_map[HW_];             // hw -> out-pixel slot or -1

// ============================================================
// scatter map
// ============================================================
__global__ void map_init_kernel() {
    int i = blockIdx.x * blockDim.x + threadIdx.x;
    if (i < HW_) g_map[i] = -1;
}
__global__ void map_set_kernel(const int* __restrict__ idx_out) {
    int n = blockIdx.x * blockDim.x + threadIdx.x;
    if (n < N_) g_map[idx_out[n]] = n;
}

// ============================================================
// Projection GEMM: out[b,n,o] = bias[o] + sum_c W[o,c] * f[b,c,idx[n]]
// which: 0 -> g_Q, 1 -> g_K, 2 -> g_V
// block tile: 64 n x 32 o, K chunks of 32. 256 threads.
// ============================================================
__global__ void __launch_bounds__(256) proj_kernel(
    const float* __restrict__ f, const int* __restrict__ idx,
    const float* __restrict__ W, const float* __restrict__ bias, int which)
{
    __shared__ __align__(16) float As[32][68];  // [c][n]
    __shared__ float Ws[32][33];                // [o][c]
    __shared__ int   sidx[64];

    const int b  = blockIdx.z;
    const int n0 = blockIdx.x * 64;
    const int o0 = blockIdx.y * 32;
    const int t  = threadIdx.x;
    const int to = t & 15;       // 16 threads over o (x2 each)
    const int tn = t >> 4;       // 16 threads over n (x4 each)

    int outDim = (which == 2) ? DV_ : FOUT_;
    float* outp = (which == 0) ? g_Q : (which == 1) ? g_K : g_V;

    if (t < 64) sidx[t] = idx[n0 + t];
    __syncthreads();

    float acc[4][2] = {};
    const float* fb = f + (size_t)b * C_ * HW_;

    for (int cc = 0; cc < C_; cc += 32) {
#pragma unroll
        for (int r = 0; r < 8; r++) {
            int lin = t + r * 256;
            int n = lin & 63, c = lin >> 6;
            As[c][n] = fb[(cc + c) * HW_ + sidx[n]];
        }
#pragma unroll
        for (int r = 0; r < 4; r++) {
            int lin = t + r * 256;
            int c = lin & 31, o = lin >> 5;
            Ws[o][c] = W[(o0 + o) * C_ + cc + c];
        }
        __syncthreads();
#pragma unroll
        for (int c = 0; c < 32; c++) {
            float4 a = *(const float4*)&As[c][tn * 4];
            float w0 = Ws[2 * to][c];
            float w1 = Ws[2 * to + 1][c];
            acc[0][0] += a.x * w0;  acc[0][1] += a.x * w1;
            acc[1][0] += a.y * w0;  acc[1][1] += a.y * w1;
            acc[2][0] += a.z * w0;  acc[2][1] += a.z * w1;
            acc[3][0] += a.w * w0;  acc[3][1] += a.w * w1;
        }
        __syncthreads();
    }

    float b0 = bias[o0 + 2 * to];
    float b1 = bias[o0 + 2 * to + 1];
#pragma unroll
    for (int i = 0; i < 4; i++) {
        int n = n0 + tn * 4 + i;
        float2 v = make_float2(acc[i][0] + b0, acc[i][1] + b1);
        *(float2*)&outp[((size_t)b * N_ + n) * outDim + o0 + 2 * to] = v;
    }
}

// ============================================================
// Flash attention: O[b,q,:] = softmax_k(Q[b,q]·K[b,k]) @ V[b,k,:]
// BQ = BK = 64, d_qk = 32, d_v = 256. 256 threads, 2 CTA/SM.
// thread (tq = t>>4, tk = t&15): owns 4 q rows, 16 v-cols
// (d = j*64 + 4*tk + dd), and in S-phase the 4 k rows {tk+16j}.
// ============================================================
__global__ void __launch_bounds__(256, 2) flash_kernel() {
    extern __shared__ __align__(16) float sm[];
    float* Qs   = sm;                 // 64*32   = 2048
    float* Ks   = sm + 2048;          // 64*33   = 2112 (stride 33: conflict-free)
    float* Vs   = sm + 4160;          // 64*256  = 16384
    float* Ps   = sm + 20544;         // 64*68   = 4352 (P[k][q], stride 68)
    float* rowm = sm + 24896;         // 64
    float* rowl = sm + 24960;         // 64
    float* corr = sm + 25024;         // 64  -> total 25088 floats = 100352 B

    const int b  = blockIdx.y;
    const int q0 = blockIdx.x * 64;
    const int t  = threadIdx.x;
    const int tq = t >> 4;
    const int tk = t & 15;

    // load Q tile (coalesced)
    const float* Qg = g_Q + ((size_t)b * N_ + q0) * FOUT_;
#pragma unroll
    for (int i = 0; i < 8; i++) Qs[t + i * 256] = Qg[t + i * 256];
    if (t < 64) { rowm[t] = -1e30f; rowl[t] = 0.0f; }

    float acc[4][16];
#pragma unroll
    for (int i = 0; i < 4; i++)
#pragma unroll
        for (int j = 0; j < 16; j++) acc[i][j] = 0.0f;

    __syncthreads();

    for (int k0 = 0; k0 < N_; k0 += 64) {
        // load K tile into stride-33 layout
        const float* Kg = g_K + ((size_t)b * N_ + k0) * FOUT_;
#pragma unroll
        for (int i = 0; i < 8; i++) {
            int e = t + i * 256;
            Ks[(e >> 5) * 33 + (e & 31)] = Kg[e];
        }
        // load V tile (float4 coalesced)
        const float4* Vg = (const float4*)(g_V + ((size_t)b * N_ + k0) * DV_);
        float4* Vs4 = (float4*)Vs;
#pragma unroll
        for (int i = 0; i < 16; i++) Vs4[t + i * 256] = Vg[t + i * 256];
        __syncthreads();

        // S = Q K^T ; this thread: k rows {tk + 16j}, q rows {4tq + i}
        float s[4][4] = {};
#pragma unroll
        for (int d = 0; d < 32; d++) {
            float kv[4], qv[4];
#pragma unroll
            for (int j = 0; j < 4; j++) kv[j] = Ks[(tk + 16 * j) * 33 + d];
#pragma unroll
            for (int i = 0; i < 4; i++) qv[i] = Qs[(4 * tq + i) * 32 + d];
#pragma unroll
            for (int j = 0; j < 4; j++)
#pragma unroll
                for (int i = 0; i < 4; i++) s[j][i] += kv[j] * qv[i];
        }
#pragma unroll
        for (int j = 0; j < 4; j++)
#pragma unroll
            for (int i = 0; i < 4; i++)
                Ps[(tk + 16 * j) * 68 + 4 * tq + i] = s[j][i];
        __syncthreads();

        // online softmax over this key tile (threads 0..63 own one q row each)
        if (t < 64) {
            float mx = rowm[t];
#pragma unroll 8
            for (int k = 0; k < 64; k++) mx = fmaxf(mx, Ps[k * 68 + t]);
            float c = __expf(rowm[t] - mx);
            float l = rowl[t] * c;
#pragma unroll 8
            for (int k = 0; k < 64; k++) {
                float e = __expf(Ps[k * 68 + t] - mx);
                Ps[k * 68 + t] = e;
                l += e;
            }
            rowm[t] = mx; rowl[t] = l; corr[t] = c;
        }
        __syncthreads();

        // rescale accumulators
        float cr[4];
#pragma unroll
        for (int i = 0; i < 4; i++) cr[i] = corr[4 * tq + i];
#pragma unroll
        for (int i = 0; i < 4; i++)
#pragma unroll
            for (int j = 0; j < 16; j++) acc[i][j] *= cr[i];

        // O += P @ V  (64 FFMA per 5 LDS.128 per k)
#pragma unroll 4
        for (int k = 0; k < 64; k++) {
            float4 p = *(const float4*)&Ps[k * 68 + 4 * tq];
            const float* vrow = &Vs[k * DV_ + 4 * tk];
            float4 v[4];
            v[0] = *(const float4*)&vrow[0];
            v[1] = *(const float4*)&vrow[64];
            v[2] = *(const float4*)&vrow[128];
            v[3] = *(const float4*)&vrow[192];
            float pp[4] = {p.x, p.y, p.z, p.w};
#pragma unroll
            for (int i = 0; i < 4; i++) {
#pragma unroll
                for (int j = 0; j < 4; j++) {
                    acc[i][4 * j + 0] += pp[i] * v[j].x;
                    acc[i][4 * j + 1] += pp[i] * v[j].y;
                    acc[i][4 * j + 2] += pp[i] * v[j].z;
                    acc[i][4 * j + 3] += pp[i] * v[j].w;
                }
            }
        }
        __syncthreads();
    }

    // normalize + write O (coalesced float4)
    float inv[4];
#pragma unroll
    for (int i = 0; i < 4; i++) inv[i] = 1.0f / rowl[4 * tq + i];
    float* Og = g_O + ((size_t)b * N_ + q0) * DV_;
#pragma unroll
    for (int i = 0; i < 4; i++) {
        int q = 4 * tq + i;
#pragma unroll
        for (int j = 0; j < 4; j++) {
            float4 o = make_float4(acc[i][4 * j + 0] * inv[i],
                                   acc[i][4 * j + 1] * inv[i],
                                   acc[i][4 * j + 2] * inv[i],
                                   acc[i][4 * j + 3] * inv[i]);
            *(float4*)&Og[q * DV_ + 64 * j + 4 * tk] = o;
        }
    }
}

// ============================================================
// Epilogue: scatter r_v into f -> f_reshape, then mask blend -> f_out
// out[0:TOT] = f_reshape, out[TOT:2*TOT] = f_out
// ============================================================
__global__ void __launch_bounds__(256) epilogue_kernel(
    const float* __restrict__ f, const float* __restrict__ mask,
    const float* __restrict__ gamma, float* __restrict__ out)
{
    int gid = blockIdx.x * 256 + threadIdx.x;
    if (gid >= TOT_) return;
    int hw = gid % HW_;
    int bc = gid / HW_;
    int c  = bc % C_;
    int b  = bc / C_;

    int slot = g_map[hw];
    float val = (slot >= 0) ? g_O[((size_t)b * N_ + slot) * DV_ + c] : f[gid];
    float m = mask[b * HW_ + hw];
    float g = gamma[0];

    out[gid]        = val;
    out[gid + TOT_] = val * (1.0f + (1.0f - m) * g);
}

// ============================================================
// launch
// ============================================================
extern "C" void kernel_launch(void* const* d_in, const int* in_sizes, int n_in,
                              void* d_out, int out_size) {
    const float* f       = (const float*)d_in[0];
    const float* mask    = (const float*)d_in[1];
    const int*   idx_out = (const int*)d_in[2];
    const int*   idx_in  = (const int*)d_in[3];
    const float* Wq      = (const float*)d_in[4];
    const float* bq      = (const float*)d_in[5];
    const float* Wk      = (const float*)d_in[6];
    const float* bk      = (const float*)d_in[7];
    const float* Wv      = (const float*)d_in[8];
    const float* bv      = (const float*)d_in[9];
    const float* gamma   = (const float*)d_in[10];
    float* out = (float*)d_out;

    cudaFuncSetAttribute(flash_kernel,
                         cudaFuncAttributeMaxDynamicSharedMemorySize, 100352);

    map_init_kernel<<<(HW_ + 255) / 256, 256>>>();
    map_set_kernel<<<(N_ + 255) / 256, 256>>>(idx_out);

    proj_kernel<<<dim3(N_ / 64, 1, B_), 256>>>(f, idx_out, Wq, bq, 0);  // Q
    proj_kernel<<<dim3(N_ / 64, 1, B_), 256>>>(f, idx_in,  Wk, bk, 1);  // K
    proj_kernel<<<dim3(N_ / 64, 8, B_), 256>>>(f, idx_in,  Wv, bv, 2);  // V

    flash_kernel<<<dim3(N_ / 64, B_), 256, 100352>>>();

    epilogue_kernel<<<(TOT_ + 255) / 256, 256>>>(f, mask, gamma, out);
}